// round 1
// baseline (speedup 1.0000x reference)
#include <cuda_runtime.h>
#include <math.h>

#define BB 2
#define MM 4096
#define CC 256
#define HW 64
#define PYR_POS (4096 + 1024 + 256 + 64)   // 5440 spatial positions per batch
#define NBINS 512                           // 2 batches * 16 * 16
#define QCAP 96                             // max queries tracked per bin (mean ~16)
#define PATCH_MAXF (13 * 13 * CC)           // floats

// ---------------- device scratch (static: no allocations allowed) ----------
__device__ float g_pyr[BB * PYR_POS * CC];  // channel-last fmap2 pyramid (~11 MB)
__device__ int   g_cnt[NBINS];
__device__ int   g_qlist[NBINS * QCAP];

// ---------------- kernel 1: transpose fmap2 (B,C,H,W) -> (B, H*W, C) -------
__global__ void transpose_kernel(const float* __restrict__ f2) {
    __shared__ float tile[32][33];
    int b  = blockIdx.z;
    int p0 = blockIdx.x * 32;   // spatial
    int c0 = blockIdx.y * 32;   // channel
    int tx = threadIdx.x, ty = threadIdx.y;
    // coalesced read along spatial dim
    tile[ty][tx] = f2[((size_t)b * CC + (c0 + ty)) * (HW * HW) + p0 + tx];
    __syncthreads();
    // coalesced write along channel dim
    g_pyr[((size_t)b * PYR_POS + (p0 + ty)) * CC + c0 + tx] = tile[tx][ty];
}

// ---------------- kernel 2: 2x2 avg pool on channel-last pyramid level -----
__global__ void pool_kernel(int in_off, int out_off, int Wout) {
    int c = threadIdx.x;                 // 256 threads = channels
    int r = blockIdx.x;
    int b = r / (Wout * Wout); r -= b * Wout * Wout;
    int y = r / Wout, x = r - (r / Wout) * Wout;
    int Win = Wout * 2;
    const float* in  = g_pyr + ((size_t)b * PYR_POS + in_off) * CC;
    float*       out = g_pyr + ((size_t)b * PYR_POS + out_off) * CC;
    float v = 0.25f * (in[((2 * y)     * Win + 2 * x)     * CC + c]
                     + in[((2 * y)     * Win + 2 * x + 1) * CC + c]
                     + in[((2 * y + 1) * Win + 2 * x)     * CC + c]
                     + in[((2 * y + 1) * Win + 2 * x + 1) * CC + c]);
    out[(y * Wout + x) * CC + c] = v;
}

// ---------------- kernel 3/4: bin queries by floor(centroid)/4 -------------
__global__ void zero_kernel() {
    if (threadIdx.x < NBINS) g_cnt[threadIdx.x] = 0;
}

__global__ void hist_kernel(const float* __restrict__ cen) {
    int t = blockIdx.x * blockDim.x + threadIdx.x;
    if (t >= BB * MM) return;
    float cx = cen[2 * t], cy = cen[2 * t + 1];
    int bx = ((int)cx) >> 2;  bx = bx < 0 ? 0 : (bx > 15 ? 15 : bx);
    int by = ((int)cy) >> 2;  by = by < 0 ? 0 : (by > 15 ? 15 : by);
    int b = t / MM, m = t - b * MM;
    int bin = (b << 8) | (by << 4) | bx;
    int pos = atomicAdd(&g_cnt[bin], 1);
    if (pos < QCAP) g_qlist[bin * QCAP + pos] = m;
}

// ---------------- kernel 5: main sparse-correlation lookup -----------------
// One block per (batch, 4x4-cell bin). Per level: stage the union patch
// (channel-last) in SMEM, then warp-per-query: 100 integer-lattice dots
// (lanes = 8 channels each, butterfly reduce), then 81 bilinear outputs.
__global__ __launch_bounds__(256) void corr_kernel(const float* __restrict__ f1,
                                                   const float* __restrict__ cen,
                                                   float* __restrict__ out) {
    extern __shared__ float sm[];
    float* patch = sm;                  // up to 13*13*256 floats
    float* Dall  = sm + PATCH_MAXF;     // 8 warps * 100 dots

    int bin = blockIdx.x;
    int b  = bin >> 8;
    int by = (bin >> 4) & 15, bx = bin & 15;
    int nq = g_cnt[bin];  if (nq > QCAP) nq = QCAP;

    int tid = threadIdx.x, lane = tid & 31, w = tid >> 5;
    const float* pyrb = g_pyr + (size_t)b * PYR_POS * CC;
    const int lvl_off[4] = {0, 4096, 5120, 5376};

    for (int lvl = 0; lvl < 4; lvl++) {
        int Wl = HW >> lvl;
        int ixmin = (4 * bx) >> lvl, ixmax = (4 * bx + 3) >> lvl;
        int iymin = (4 * by) >> lvl, iymax = (4 * by + 3) >> lvl;
        int px0 = ixmin - 4, py0 = iymin - 4;
        int pw = ixmax - ixmin + 10, ph = iymax - iymin + 10;

        __syncthreads();   // protect previous level's patch until all reads done
        {   // cooperative patch load, zero-fill outside [0,Wl)
            int nf4 = pw * ph * (CC / 4);
            const float4* src = (const float4*)(pyrb + (size_t)lvl_off[lvl] * CC);
            float4* dst = (float4*)patch;
            for (int idx = tid; idx < nf4; idx += 256) {
                int pos = idx >> 6, c4 = idx & 63;
                int ly = pos / pw, lx = pos - ly * pw;
                int gx = px0 + lx, gy = py0 + ly;
                float4 v = make_float4(0.f, 0.f, 0.f, 0.f);
                if ((unsigned)gx < (unsigned)Wl && (unsigned)gy < (unsigned)Wl)
                    v = src[(gy * Wl + gx) * (CC / 4) + c4];
                dst[pos * (CC / 4) + c4] = v;
            }
        }
        __syncthreads();

        float scale = 1.0f / (float)(1 << lvl);
        float* D = Dall + w * 100;

        for (int q = w; q < nq; q += 8) {
            int m = g_qlist[bin * QCAP + q];
            // fmap1 row: 8 channels per lane, in registers
            const float4* A = (const float4*)(f1 + ((size_t)b * MM + m) * CC) + lane * 2;
            float4 a0 = A[0], a1 = A[1];
            float cx = cen[((size_t)b * MM + m) * 2 + 0];
            float cy = cen[((size_t)b * MM + m) * 2 + 1];
            float sx = cx * scale, sy = cy * scale;
            float fix = floorf(sx), fiy = floorf(sy);
            float fx = sx - fix, fy = sy - fiy;
            int ox = (int)fix - 4 - px0;
            int oy = (int)fiy - 4 - py0;

            // 100 integer-lattice dot products (10x10), 2 positions in flight
            for (int py = 0; py < 10; py++) {
                const float* row = patch + ((oy + py) * pw + ox) * CC;
                #pragma unroll
                for (int px = 0; px < 10; px += 2) {
                    const float4* v0p = (const float4*)(row + px * CC) + lane * 2;
                    const float4* v1p = (const float4*)(row + (px + 1) * CC) + lane * 2;
                    float4 u0 = v0p[0], u1 = v0p[1];
                    float4 t0 = v1p[0], t1 = v1p[1];
                    float s0 = a0.x * u0.x + a0.y * u0.y + a0.z * u0.z + a0.w * u0.w
                             + a1.x * u1.x + a1.y * u1.y + a1.z * u1.z + a1.w * u1.w;
                    float s1 = a0.x * t0.x + a0.y * t0.y + a0.z * t0.z + a0.w * t0.w
                             + a1.x * t1.x + a1.y * t1.y + a1.z * t1.z + a1.w * t1.w;
                    #pragma unroll
                    for (int o = 16; o > 0; o >>= 1) {
                        s0 += __shfl_xor_sync(0xffffffffu, s0, o);
                        s1 += __shfl_xor_sync(0xffffffffu, s1, o);
                    }
                    if (lane == 0) { D[py * 10 + px] = s0; D[py * 10 + px + 1] = s1; }
                }
            }
            __syncwarp();

            // 81 bilinear outputs: k = i*9 + j, x-offset = i-4, y-offset = j-4
            float wx1 = fx, wx0 = 1.f - fx, wy1 = fy, wy0 = 1.f - fy;
            for (int e = lane; e < 81; e += 32) {
                int i = e / 9, j = e - (e / 9) * 9;
                float d00 = D[j * 10 + i],       d01 = D[j * 10 + i + 1];
                float d10 = D[(j + 1) * 10 + i], d11 = D[(j + 1) * 10 + i + 1];
                float val = wy0 * (wx0 * d00 + wx1 * d01)
                          + wy1 * (wx0 * d10 + wx1 * d11);
                out[((size_t)b * 324 + lvl * 81 + e) * MM + m] = val;
            }
            __syncwarp();   // D reused by next query of this warp
        }
    }
}

// ---------------- launch ----------------------------------------------------
extern "C" void kernel_launch(void* const* d_in, const int* in_sizes, int n_in,
                              void* d_out, int out_size) {
    const float* f1  = (const float*)d_in[0];   // (B, M, C)
    const float* f2  = (const float*)d_in[1];   // (B, C, H, W)
    const float* cen = (const float*)d_in[2];   // (B, M, 2)
    float* out = (float*)d_out;                 // (B, 324, M)

    size_t smem = (size_t)(PATCH_MAXF + 8 * 100) * sizeof(float);  // ~176 KB
    cudaFuncSetAttribute(corr_kernel, cudaFuncAttributeMaxDynamicSharedMemorySize,
                         (int)smem);

    transpose_kernel<<<dim3(HW * HW / 32, CC / 32, BB), dim3(32, 32)>>>(f2);
    pool_kernel<<<BB * 32 * 32, 256>>>(0,    4096, 32);
    pool_kernel<<<BB * 16 * 16, 256>>>(4096, 5120, 16);
    pool_kernel<<<BB * 8 * 8,   256>>>(5120, 5376, 8);
    zero_kernel<<<1, 512>>>();
    hist_kernel<<<(BB * MM + 255) / 256, 256>>>(cen);
    corr_kernel<<<NBINS, 256, smem>>>(f1, cen, out);
}

// round 2
// speedup vs baseline: 2.3614x; 2.3614x over previous
#include <cuda_runtime.h>
#include <math.h>

#define BB 2
#define MM 4096
#define CC 256
#define HW 64
#define PYR_POS (4096 + 1024 + 256 + 64)
#define NBINS 512                // 2 batches * 16 * 16
#define QCAP 96
#define NPOS_MAX 169             // 13*13 at level 0
#define PSTR 260                 // padded row stride (floats) -> conflict-free frags
#define DSTR 171

// device scratch (no allocations allowed)
__device__ float g_pyr[BB * PYR_POS * CC];
__device__ int   g_cnt[NBINS];
__device__ int   g_qlist[NBINS * QCAP];

// packed f32x2 FMA: d.lo += a.lo*b.lo ; d.hi += a.hi*b.hi
__device__ __forceinline__ void fma2(unsigned long long& d,
                                     unsigned long long a,
                                     unsigned long long b) {
    asm("fma.rn.f32x2 %0, %1, %2, %0;" : "+l"(d) : "l"(a), "l"(b));
}
__device__ __forceinline__ float unpack_sum(unsigned long long v) {
    return __uint_as_float((unsigned)v) + __uint_as_float((unsigned)(v >> 32));
}

// ---------------- transpose fmap2 (B,C,H,W) -> (B, H*W, C) ------------------
__global__ void transpose_kernel(const float* __restrict__ f2) {
    __shared__ float tile[32][33];
    int b  = blockIdx.z;
    int p0 = blockIdx.x * 32;
    int c0 = blockIdx.y * 32;
    int tx = threadIdx.x, ty = threadIdx.y;
    tile[ty][tx] = f2[((size_t)b * CC + (c0 + ty)) * (HW * HW) + p0 + tx];
    __syncthreads();
    g_pyr[((size_t)b * PYR_POS + (p0 + ty)) * CC + c0 + tx] = tile[tx][ty];
}

// ---------------- 2x2 avg pool on channel-last level ------------------------
__global__ void pool_kernel(int in_off, int out_off, int Wout) {
    int c = threadIdx.x;
    int r = blockIdx.x;
    int b = r / (Wout * Wout); r -= b * Wout * Wout;
    int y = r / Wout, x = r - (r / Wout) * Wout;
    int Win = Wout * 2;
    const float* in  = g_pyr + ((size_t)b * PYR_POS + in_off) * CC;
    float*       out = g_pyr + ((size_t)b * PYR_POS + out_off) * CC;
    float v = 0.25f * (in[((2 * y)     * Win + 2 * x)     * CC + c]
                     + in[((2 * y)     * Win + 2 * x + 1) * CC + c]
                     + in[((2 * y + 1) * Win + 2 * x)     * CC + c]
                     + in[((2 * y + 1) * Win + 2 * x + 1) * CC + c]);
    out[(y * Wout + x) * CC + c] = v;
}

__global__ void zero_kernel() {
    if (threadIdx.x < NBINS) g_cnt[threadIdx.x] = 0;
}

__global__ void hist_kernel(const float* __restrict__ cen) {
    int t = blockIdx.x * blockDim.x + threadIdx.x;
    if (t >= BB * MM) return;
    float cx = cen[2 * t], cy = cen[2 * t + 1];
    int bx = ((int)cx) >> 2;  bx = bx < 0 ? 0 : (bx > 15 ? 15 : bx);
    int by = ((int)cy) >> 2;  by = by < 0 ? 0 : (by > 15 ? 15 : by);
    int b = t / MM, m = t - b * MM;
    int bin = (b << 8) | (by << 4) | bx;
    int pos = atomicAdd(&g_cnt[bin], 1);
    if (pos < QCAP) g_qlist[bin * QCAP + pos] = m;
}

// ---------------- main: per-(bin,level) register-tiled GEMM ------------------
// Block = one (bin, level). Stage union patch P [Npos][256] + A [16][256] in
// SMEM (stride PSTR). Thread computes 4q x 4pos with f32x2 packed FMAs.
// Then bilinear epilogue from D (SMEM) to global output.
__global__ __launch_bounds__(256) void corr_kernel(const float* __restrict__ f1,
                                                   const float* __restrict__ cen,
                                                   float* __restrict__ out) {
    extern __shared__ float sm[];
    float* Ps = sm;                          // NPOS_MAX * PSTR
    float* As = sm + NPOS_MAX * PSTR;        // 16 * PSTR
    float* Ds = As + 16 * PSTR;              // 16 * DSTR

    int blk = blockIdx.x;
    int lvl = blk & 3;
    int bin = blk >> 2;
    int b  = bin >> 8;
    int by = (bin >> 4) & 15, bx = bin & 15;
    int nq = g_cnt[bin]; if (nq > QCAP) nq = QCAP;
    if (nq == 0) return;

    const int lvl_off[4] = {0, 4096, 5120, 5376};
    int Wl = HW >> lvl;
    int ixmin = (4 * bx) >> lvl, ixmax = (4 * bx + 3) >> lvl;
    int iymin = (4 * by) >> lvl, iymax = (4 * by + 3) >> lvl;
    int px0 = ixmin - 4, py0 = iymin - 4;
    int pw = ixmax - ixmin + 10, ph = iymax - iymin + 10;
    int Npos = pw * ph;

    int tid = threadIdx.x, lane = tid & 31, w = tid >> 5;

    // ---- stage patch (zero-filled outside [0,Wl)^2), channel-last ----------
    {
        const float4* src = (const float4*)(g_pyr + ((size_t)b * PYR_POS + lvl_off[lvl]) * CC);
        int nf4 = Npos * (CC / 4);
        for (int idx = tid; idx < nf4; idx += 256) {
            int pos = idx >> 6, c4 = idx & 63;
            int ly = pos / pw, lx = pos - ly * pw;
            int gx = px0 + lx, gy = py0 + ly;
            float4 v = make_float4(0.f, 0.f, 0.f, 0.f);
            if ((unsigned)gx < (unsigned)Wl && (unsigned)gy < (unsigned)Wl)
                v = src[(gy * Wl + gx) * (CC / 4) + c4];
            *(float4*)&Ps[pos * PSTR + c4 * 4] = v;
        }
    }

    int qsel = lane >> 3;        // 0..3  (queries qsel, qsel+4, qsel+8, qsel+12)
    int psel = lane & 7;         // 0..7  (positions wbase+psel+8*pi)
    int wbase = w * 32;
    float scale = 1.0f / (float)(1 << lvl);

    for (int q0 = 0; q0 < nq; q0 += 16) {
        int qcnt = nq - q0; if (qcnt > 16) qcnt = 16;

        __syncthreads();   // patch ready / previous chunk's As,Ds consumed
        // ---- stage A: 16 query feature rows -------------------------------
        for (int idx = tid; idx < 16 * 64; idx += 256) {
            int qq = idx >> 6, c4 = idx & 63;
            int qv = (qq < qcnt) ? qq : 0;
            int m = g_qlist[bin * QCAP + q0 + qv];
            *(float4*)&As[qq * PSTR + c4 * 4] =
                ((const float4*)(f1 + ((size_t)b * MM + m) * CC))[c4];
        }
        __syncthreads();

        // ---- GEMM tile: 4q x 4pos per thread, f32x2 packed ----------------
        if (wbase < Npos) {
            int pidx[4];
            #pragma unroll
            for (int pi = 0; pi < 4; pi++) {
                int p = wbase + psel + 8 * pi;
                pidx[pi] = (p < Npos) ? p : (Npos - 1);
            }
            unsigned long long acc[4][4];
            #pragma unroll
            for (int qi = 0; qi < 4; qi++)
                #pragma unroll
                for (int pi = 0; pi < 4; pi++) acc[qi][pi] = 0ull;

            #pragma unroll 2
            for (int c = 0; c < CC; c += 4) {
                ulonglong2 a[4], p[4];
                #pragma unroll
                for (int qi = 0; qi < 4; qi++)
                    a[qi] = *(const ulonglong2*)&As[(qsel + 4 * qi) * PSTR + c];
                #pragma unroll
                for (int pi = 0; pi < 4; pi++)
                    p[pi] = *(const ulonglong2*)&Ps[pidx[pi] * PSTR + c];
                #pragma unroll
                for (int qi = 0; qi < 4; qi++)
                    #pragma unroll
                    for (int pi = 0; pi < 4; pi++) {
                        fma2(acc[qi][pi], a[qi].x, p[pi].x);
                        fma2(acc[qi][pi], a[qi].y, p[pi].y);
                    }
            }

            #pragma unroll
            for (int qi = 0; qi < 4; qi++)
                #pragma unroll
                for (int pi = 0; pi < 4; pi++) {
                    int p = wbase + psel + 8 * pi;
                    if (p < Npos)
                        Ds[(qsel + 4 * qi) * DSTR + p] = unpack_sum(acc[qi][pi]);
                }
        }
        __syncthreads();

        // ---- bilinear epilogue: warp per query ----------------------------
        for (int qq = w; qq < qcnt; qq += 8) {
            int m = g_qlist[bin * QCAP + q0 + qq];
            float cx = cen[((size_t)b * MM + m) * 2 + 0];
            float cy = cen[((size_t)b * MM + m) * 2 + 1];
            float sx = cx * scale, sy = cy * scale;
            float fix = floorf(sx), fiy = floorf(sy);
            float fx = sx - fix, fy = sy - fiy;
            int ox = (int)fix - 4 - px0;
            int oy = (int)fiy - 4 - py0;
            float wx1 = fx, wx0 = 1.f - fx, wy1 = fy, wy0 = 1.f - fy;
            const float* Dq = Ds + qq * DSTR;
            for (int e = lane; e < 81; e += 32) {
                int i = e / 9, j = e - (e / 9) * 9;   // x-offset i-4, y-offset j-4
                int base = (oy + j) * pw + (ox + i);
                float d00 = Dq[base],      d01 = Dq[base + 1];
                float d10 = Dq[base + pw], d11 = Dq[base + pw + 1];
                float val = wy0 * (wx0 * d00 + wx1 * d01)
                          + wy1 * (wx0 * d10 + wx1 * d11);
                out[((size_t)b * 324 + lvl * 81 + e) * MM + m] = val;
            }
        }
    }
}

// ---------------- launch ----------------------------------------------------
extern "C" void kernel_launch(void* const* d_in, const int* in_sizes, int n_in,
                              void* d_out, int out_size) {
    const float* f1  = (const float*)d_in[0];
    const float* f2  = (const float*)d_in[1];
    const float* cen = (const float*)d_in[2];
    float* out = (float*)d_out;

    size_t smem = (size_t)(NPOS_MAX * PSTR + 16 * PSTR + 16 * DSTR) * sizeof(float);
    cudaFuncSetAttribute(corr_kernel, cudaFuncAttributeMaxDynamicSharedMemorySize,
                         (int)smem);

    transpose_kernel<<<dim3(HW * HW / 32, CC / 32, BB), dim3(32, 32)>>>(f2);
    pool_kernel<<<BB * 32 * 32, 256>>>(0,    4096, 32);
    pool_kernel<<<BB * 16 * 16, 256>>>(4096, 5120, 16);
    pool_kernel<<<BB * 8 * 8,   256>>>(5120, 5376, 8);
    zero_kernel<<<1, 512>>>();
    hist_kernel<<<(BB * MM + 255) / 256, 256>>>(cen);
    corr_kernel<<<NBINS * 4, 256, smem>>>(f1, cen, out);
}

// round 3
// speedup vs baseline: 2.8722x; 1.2163x over previous
#include <cuda_runtime.h>
#include <math.h>

#define BB 2
#define MM 4096
#define CC 256
#define HW 64
#define PYR_POS (4096 + 1024 + 256 + 64)
#define NBINS 512                // 2 batches * 16 * 16
#define QCAP 96
#define NPOS_MAX 169             // 13*13 at level 0
#define PSTRH 132                // padded half-row stride (128 ch + 4)
#define DSTR 200                 // D stride: 200 % 32 == 8 -> conflict-free qsel groups

// device scratch (no allocations allowed)
__device__ float g_pyr[BB * PYR_POS * CC];
__device__ int   g_cnt[NBINS];
__device__ int   g_qlist[NBINS * QCAP];

// packed f32x2 FMA: d.lo += a.lo*b.lo ; d.hi += a.hi*b.hi
__device__ __forceinline__ void fma2(unsigned long long& d,
                                     unsigned long long a,
                                     unsigned long long b) {
    asm("fma.rn.f32x2 %0, %1, %2, %0;" : "+l"(d) : "l"(a), "l"(b));
}
__device__ __forceinline__ float unpack_sum(unsigned long long v) {
    return __uint_as_float((unsigned)v) + __uint_as_float((unsigned)(v >> 32));
}

// cp.async 16B with zero-fill when srcsize==0
__device__ __forceinline__ void cp16(unsigned smem_addr, const void* gptr, int srcsize) {
    asm volatile("cp.async.cg.shared.global [%0], [%1], 16, %2;\n"
                 :: "r"(smem_addr), "l"(gptr), "r"(srcsize));
}
__device__ __forceinline__ void cp_commit_wait() {
    asm volatile("cp.async.commit_group;\n");
    asm volatile("cp.async.wait_group 0;\n" ::: "memory");
}

// ---------------- transpose fmap2 (B,C,H,W) -> (B, H*W, C) ------------------
__global__ void transpose_kernel(const float* __restrict__ f2) {
    __shared__ float tile[32][33];
    int b  = blockIdx.z;
    int p0 = blockIdx.x * 32;
    int c0 = blockIdx.y * 32;
    int tx = threadIdx.x, ty = threadIdx.y;
    tile[ty][tx] = f2[((size_t)b * CC + (c0 + ty)) * (HW * HW) + p0 + tx];
    __syncthreads();
    g_pyr[((size_t)b * PYR_POS + (p0 + ty)) * CC + c0 + tx] = tile[tx][ty];
}

// ---------------- 2x2 avg pool on channel-last level ------------------------
__global__ void pool_kernel(int in_off, int out_off, int Wout) {
    int c = threadIdx.x;
    int r = blockIdx.x;
    int b = r / (Wout * Wout); r -= b * Wout * Wout;
    int y = r / Wout, x = r - (r / Wout) * Wout;
    int Win = Wout * 2;
    const float* in  = g_pyr + ((size_t)b * PYR_POS + in_off) * CC;
    float*       out = g_pyr + ((size_t)b * PYR_POS + out_off) * CC;
    float v = 0.25f * (in[((2 * y)     * Win + 2 * x)     * CC + c]
                     + in[((2 * y)     * Win + 2 * x + 1) * CC + c]
                     + in[((2 * y + 1) * Win + 2 * x)     * CC + c]
                     + in[((2 * y + 1) * Win + 2 * x + 1) * CC + c]);
    out[(y * Wout + x) * CC + c] = v;
}

__global__ void zero_kernel() {
    if (threadIdx.x < NBINS) g_cnt[threadIdx.x] = 0;
}

__global__ void hist_kernel(const float* __restrict__ cen) {
    int t = blockIdx.x * blockDim.x + threadIdx.x;
    if (t >= BB * MM) return;
    float cx = cen[2 * t], cy = cen[2 * t + 1];
    int bx = ((int)cx) >> 2;  bx = bx < 0 ? 0 : (bx > 15 ? 15 : bx);
    int by = ((int)cy) >> 2;  by = by < 0 ? 0 : (by > 15 ? 15 : by);
    int b = t / MM, m = t - b * MM;
    int bin = (b << 8) | (by << 4) | bx;
    int pos = atomicAdd(&g_cnt[bin], 1);
    if (pos < QCAP) g_qlist[bin * QCAP + pos] = m;
}

// ---------------- main: per-(bin,level) register-tiled GEMM ------------------
// K dim split into two 128-ch halves staged via cp.async into a half-size
// patch buffer -> 108 KB smem -> 2 CTAs/SM. Thread tile 4q x 4pos, f32x2 FMAs.
__global__ __launch_bounds__(256) void corr_kernel(const float* __restrict__ f1,
                                                   const float* __restrict__ cen,
                                                   float* __restrict__ out) {
    extern __shared__ float sm[];
    float* Ps = sm;                           // NPOS_MAX * PSTRH
    float* As = sm + NPOS_MAX * PSTRH;        // 16 * PSTRH
    float* Ds = As + 16 * PSTRH;              // 16 * DSTR

    int blk = blockIdx.x;
    int lvl = blk & 3;
    int bin = blk >> 2;
    int b  = bin >> 8;
    int by = (bin >> 4) & 15, bx = bin & 15;
    int nq = g_cnt[bin]; if (nq > QCAP) nq = QCAP;
    if (nq == 0) return;

    const int lvl_off[4] = {0, 4096, 5120, 5376};
    int Wl = HW >> lvl;
    int ixmin = (4 * bx) >> lvl, ixmax = (4 * bx + 3) >> lvl;
    int iymin = (4 * by) >> lvl, iymax = (4 * by + 3) >> lvl;
    int px0 = ixmin - 4, py0 = iymin - 4;
    int pw = ixmax - ixmin + 10, ph = iymax - iymin + 10;
    int Npos = pw * ph;

    int tid = threadIdx.x, lane = tid & 31, w = tid >> 5;
    int qsel = lane >> 3;        // 0..3
    int psel = lane & 7;         // 0..7
    int wbase = w * 32;
    float scale = 1.0f / (float)(1 << lvl);

    unsigned Ps_b = (unsigned)__cvta_generic_to_shared(Ps);
    unsigned As_b = (unsigned)__cvta_generic_to_shared(As);

    int pidx[4];
    #pragma unroll
    for (int pi = 0; pi < 4; pi++) {
        int p = wbase + psel + 8 * pi;
        pidx[pi] = (p < Npos) ? p : (Npos - 1);
    }

    for (int q0 = 0; q0 < nq; q0 += 16) {
        int qcnt = nq - q0; if (qcnt > 16) qcnt = 16;

        unsigned long long acc[4][4];
        #pragma unroll
        for (int qi = 0; qi < 4; qi++)
            #pragma unroll
            for (int pi = 0; pi < 4; pi++) acc[qi][pi] = 0ull;

        for (int h = 0; h < 2; h++) {
            __syncthreads();   // previous contents fully consumed

            // ---- stage P half via cp.async (zero-fill OOB) ----------------
            const float* srcbase = g_pyr + ((size_t)b * PYR_POS + lvl_off[lvl]) * CC
                                 + h * 128;
            int nf4 = Npos * 32;
            for (int idx = tid; idx < nf4; idx += 256) {
                int pos = idx >> 5, c4 = idx & 31;
                int ly = pos / pw, lx = pos - ly * pw;
                int gx = px0 + lx, gy = py0 + ly;
                bool valid = (unsigned)gx < (unsigned)Wl && (unsigned)gy < (unsigned)Wl;
                const float* g = srcbase + ((size_t)(gy * Wl + gx)) * CC + c4 * 4;
                cp16(Ps_b + (unsigned)(pos * PSTRH + c4 * 4) * 4,
                     valid ? g : srcbase, valid ? 16 : 0);
            }
            // ---- stage A half ---------------------------------------------
            for (int idx = tid; idx < 16 * 32; idx += 256) {
                int qq = idx >> 5, c4 = idx & 31;
                int qv = (qq < qcnt) ? qq : 0;
                int m = g_qlist[bin * QCAP + q0 + qv];
                cp16(As_b + (unsigned)(qq * PSTRH + c4 * 4) * 4,
                     f1 + ((size_t)b * MM + m) * CC + h * 128 + c4 * 4, 16);
            }
            cp_commit_wait();
            __syncthreads();

            // ---- GEMM half: 4q x 4pos per thread, f32x2 -------------------
            if (wbase < Npos) {
                #pragma unroll 2
                for (int c = 0; c < 128; c += 4) {
                    ulonglong2 a[4], p[4];
                    #pragma unroll
                    for (int qi = 0; qi < 4; qi++)
                        a[qi] = *(const ulonglong2*)&As[(qsel + 4 * qi) * PSTRH + c];
                    #pragma unroll
                    for (int pi = 0; pi < 4; pi++)
                        p[pi] = *(const ulonglong2*)&Ps[pidx[pi] * PSTRH + c];
                    #pragma unroll
                    for (int qi = 0; qi < 4; qi++)
                        #pragma unroll
                        for (int pi = 0; pi < 4; pi++) {
                            fma2(acc[qi][pi], a[qi].x, p[pi].x);
                            fma2(acc[qi][pi], a[qi].y, p[pi].y);
                        }
                }
            }
        }

        // ---- write D -------------------------------------------------------
        if (wbase < Npos) {
            #pragma unroll
            for (int qi = 0; qi < 4; qi++)
                #pragma unroll
                for (int pi = 0; pi < 4; pi++) {
                    int p = wbase + psel + 8 * pi;
                    if (p < Npos)
                        Ds[(qsel + 4 * qi) * DSTR + p] = unpack_sum(acc[qi][pi]);
                }
        }
        __syncthreads();

        // ---- bilinear epilogue: warp per query -----------------------------
        for (int qq = w; qq < qcnt; qq += 8) {
            int m = g_qlist[bin * QCAP + q0 + qq];
            float cx = cen[((size_t)b * MM + m) * 2 + 0];
            float cy = cen[((size_t)b * MM + m) * 2 + 1];
            float sx = cx * scale, sy = cy * scale;
            float fix = floorf(sx), fiy = floorf(sy);
            float fx = sx - fix, fy = sy - fiy;
            int ox = (int)fix - 4 - px0;
            int oy = (int)fiy - 4 - py0;
            float wx1 = fx, wx0 = 1.f - fx, wy1 = fy, wy0 = 1.f - fy;
            const float* Dq = Ds + qq * DSTR;
            for (int e = lane; e < 81; e += 32) {
                int i = e / 9, j = e - (e / 9) * 9;   // x-offset i-4, y-offset j-4
                int base = (oy + j) * pw + (ox + i);
                float d00 = Dq[base],      d01 = Dq[base + 1];
                float d10 = Dq[base + pw], d11 = Dq[base + pw + 1];
                float val = wy0 * (wx0 * d00 + wx1 * d01)
                          + wy1 * (wx0 * d10 + wx1 * d11);
                out[((size_t)b * 324 + lvl * 81 + e) * MM + m] = val;
            }
        }
    }
}

// ---------------- launch ----------------------------------------------------
extern "C" void kernel_launch(void* const* d_in, const int* in_sizes, int n_in,
                              void* d_out, int out_size) {
    const float* f1  = (const float*)d_in[0];
    const float* f2  = (const float*)d_in[1];
    const float* cen = (const float*)d_in[2];
    float* out = (float*)d_out;

    size_t smem = (size_t)(NPOS_MAX * PSTRH + 16 * PSTRH + 16 * DSTR) * sizeof(float);
    cudaFuncSetAttribute(corr_kernel, cudaFuncAttributeMaxDynamicSharedMemorySize,
                         (int)smem);

    transpose_kernel<<<dim3(HW * HW / 32, CC / 32, BB), dim3(32, 32)>>>(f2);
    pool_kernel<<<BB * 32 * 32, 256>>>(0,    4096, 32);
    pool_kernel<<<BB * 16 * 16, 256>>>(4096, 5120, 16);
    pool_kernel<<<BB * 8 * 8,   256>>>(5120, 5376, 8);
    zero_kernel<<<1, 512>>>();
    hist_kernel<<<(BB * MM + 255) / 256, 256>>>(cen);
    corr_kernel<<<NBINS * 4, 256, smem>>>(f1, cen, out);
}

// round 4
// speedup vs baseline: 3.1860x; 1.1092x over previous
#include <cuda_runtime.h>
#include <math.h>

#define BB 2
#define MM 4096
#define CC 256
#define HW 64
#define NBINS 512                // 2 batches * 16 * 16
#define QCAP 96
#define NPOS_MAX 169             // 13*13 at level 0
#define PSTRH 132                // padded half-row stride (floats): conflict-free
#define DSTR 172

// padded pyramid: halo x,y in [-4, Wl+4] -> dims (Wl+9)^2 per level
// L0 73^2=5329, L1 41^2=1681, L2 25^2=625, L3 17^2=289 ; total 7924 positions
#define PW0 73
#define PW1 41
#define PW2 25
#define PW3 17
#define TOTPOS 7924
// layout: [b][h][pos][128]
__device__ float g_pyr2[BB * 2 * TOTPOS * 128];
__device__ int   g_cnt[NBINS];
__device__ int   g_qlist[NBINS * QCAP];

__constant__ int c_lvl_base[4] = {0, 5329, 7010, 7635};
__constant__ int c_lvl_pw[4]   = {PW0, PW1, PW2, PW3};

// ---------------- helpers ---------------------------------------------------
__device__ __forceinline__ void fma2(unsigned long long& d,
                                     unsigned long long a,
                                     unsigned long long b) {
    asm("fma.rn.f32x2 %0, %1, %2, %0;" : "+l"(d) : "l"(a), "l"(b));
}
__device__ __forceinline__ float unpack_sum(unsigned long long v) {
    return __uint_as_float((unsigned)v) + __uint_as_float((unsigned)(v >> 32));
}
__device__ __forceinline__ void bulkcp(unsigned dst, const void* src,
                                       unsigned bytes, unsigned mbar) {
    asm volatile(
        "cp.async.bulk.shared::cluster.global.mbarrier::complete_tx::bytes "
        "[%0], [%1], %2, [%3];"
        :: "r"(dst), "l"(src), "r"(bytes), "r"(mbar) : "memory");
}
__device__ __forceinline__ void mbar_init(unsigned mbar, unsigned cnt) {
    asm volatile("mbarrier.init.shared.b64 [%0], %1;" :: "r"(mbar), "r"(cnt) : "memory");
}
__device__ __forceinline__ void mbar_expect(unsigned mbar, unsigned bytes) {
    asm volatile("mbarrier.arrive.expect_tx.shared.b64 _, [%0], %1;"
                 :: "r"(mbar), "r"(bytes) : "memory");
}
__device__ __forceinline__ void mbar_wait(unsigned mbar, unsigned parity) {
    unsigned done;
    asm volatile(
        "{\n\t.reg .pred p;\n\t"
        "mbarrier.try_wait.parity.shared.b64 p, [%1], %2;\n\t"
        "selp.b32 %0, 1, 0, p;\n\t}"
        : "=r"(done) : "r"(mbar), "r"(parity) : "memory");
    while (!done) {
        asm volatile(
            "{\n\t.reg .pred p;\n\t"
            "mbarrier.try_wait.parity.shared.b64 p, [%1], %2, 0x989680;\n\t"
            "selp.b32 %0, 1, 0, p;\n\t}"
            : "=r"(done) : "r"(mbar), "r"(parity) : "memory");
    }
}

// ---------------- zero the padded pyramid (halo must be 0) ------------------
__global__ void zero_pyr_kernel() {
    float4* p = (float4*)g_pyr2;
    int n = BB * 2 * TOTPOS * 32;   // float4 count
    for (int i = blockIdx.x * blockDim.x + threadIdx.x; i < n; i += gridDim.x * blockDim.x)
        p[i] = make_float4(0.f, 0.f, 0.f, 0.f);
}

// ---------------- transpose fmap2 (B,C,H,W) -> padded L0 [b][h][pos][128] ---
__global__ void transpose_kernel(const float* __restrict__ f2) {
    __shared__ float tile[32][33];
    int b  = blockIdx.z;
    int p0 = blockIdx.x * 32;   // spatial
    int c0 = blockIdx.y * 32;   // channels
    int tx = threadIdx.x, ty = threadIdx.y;
    tile[ty][tx] = f2[((size_t)b * CC + (c0 + ty)) * (HW * HW) + p0 + tx];
    __syncthreads();
    int p = p0 + ty;
    int y = p >> 6, x = p & 63;
    int c = c0 + tx;
    int h = c >> 7, cc = c & 127;
    int pos = (y + 4) * PW0 + (x + 4);
    g_pyr2[((size_t)(b * 2 + h) * TOTPOS + pos) * 128 + cc] = tile[tx][ty];
}

// ---------------- 2x2 avg pool (padded layout, both halves) -----------------
__global__ void pool_kernel(int lin, int lout, int Wout) {
    int c = threadIdx.x;                // 256: channel
    int h = c >> 7, cc = c & 127;
    int r = blockIdx.x;
    int b = r / (Wout * Wout); r -= b * Wout * Wout;
    int y = r / Wout, x = r - (r / Wout) * Wout;
    int pwi = c_lvl_pw[lin], pwo = c_lvl_pw[lout];
    const float* in = g_pyr2 + ((size_t)(b * 2 + h) * TOTPOS + c_lvl_base[lin]) * 128 + cc;
    float* out      = g_pyr2 + ((size_t)(b * 2 + h) * TOTPOS + c_lvl_base[lout]) * 128 + cc;
    int y2 = 2 * y + 4, x2 = 2 * x + 4;
    float v = 0.25f * (in[(size_t)((y2)     * pwi + x2)     * 128]
                     + in[(size_t)((y2)     * pwi + x2 + 1) * 128]
                     + in[(size_t)((y2 + 1) * pwi + x2)     * 128]
                     + in[(size_t)((y2 + 1) * pwi + x2 + 1) * 128]);
    out[(size_t)((y + 4) * pwo + (x + 4)) * 128] = v;
}

__global__ void zero_cnt_kernel() {
    if (threadIdx.x < NBINS) g_cnt[threadIdx.x] = 0;
}

__global__ void hist_kernel(const float* __restrict__ cen) {
    int t = blockIdx.x * blockDim.x + threadIdx.x;
    if (t >= BB * MM) return;
    float cx = cen[2 * t], cy = cen[2 * t + 1];
    int bx = ((int)cx) >> 2;  bx = bx < 0 ? 0 : (bx > 15 ? 15 : bx);
    int by = ((int)cy) >> 2;  by = by < 0 ? 0 : (by > 15 ? 15 : by);
    int b = t / MM, m = t - b * MM;
    int bin = (b << 8) | (by << 4) | bx;
    int pos = atomicAdd(&g_cnt[bin], 1);
    if (pos < QCAP) g_qlist[bin * QCAP + pos] = m;
}

// ---------------- main: per-(bin,level) register-tiled GEMM ------------------
// Staging via cp.async.bulk (512 B per position/query half) + mbarrier.
// K split in two 128-ch halves (pyramid stored pre-split); acc in registers.
__global__ __launch_bounds__(256) void corr_kernel(const float* __restrict__ f1,
                                                   const float* __restrict__ cen,
                                                   float* __restrict__ out) {
    extern __shared__ float sm[];
    float* Ps = sm;                           // NPOS_MAX * PSTRH
    float* As = sm + NPOS_MAX * PSTRH;        // 16 * PSTRH
    float* Ds = As + 16 * PSTRH;              // 16 * DSTR
    __shared__ __align__(8) unsigned long long mbar_s;

    int blk = blockIdx.x;
    int lvl = blk & 3;
    int bin = blk >> 2;
    int b  = bin >> 8;
    int by = (bin >> 4) & 15, bx = bin & 15;
    int nq = g_cnt[bin]; if (nq > QCAP) nq = QCAP;
    if (nq == 0) return;

    int ixmin = (4 * bx) >> lvl, ixmax = (4 * bx + 3) >> lvl;
    int iymin = (4 * by) >> lvl, iymax = (4 * by + 3) >> lvl;
    int px0 = ixmin - 4, py0 = iymin - 4;
    int pw = ixmax - ixmin + 10, ph = iymax - iymin + 10;
    int Npos = pw * ph;
    int pwp = c_lvl_pw[lvl];

    int tid = threadIdx.x, lane = tid & 31, w = tid >> 5;
    int qsel = lane >> 3;        // 0..3
    int psel = lane & 7;         // 0..7
    int wbase = w * 32;
    float scale = 1.0f / (float)(1 << lvl);

    unsigned Ps_b = (unsigned)__cvta_generic_to_shared(Ps);
    unsigned As_b = (unsigned)__cvta_generic_to_shared(As);
    unsigned mbar = (unsigned)__cvta_generic_to_shared(&mbar_s);

    if (tid == 0) mbar_init(mbar, 1);
    __syncthreads();
    unsigned par = 0;

    int pidx[4];
    #pragma unroll
    for (int pi = 0; pi < 4; pi++) {
        int p = wbase + psel + 8 * pi;
        pidx[pi] = (p < Npos) ? p : (Npos - 1);
    }

    for (int q0 = 0; q0 < nq; q0 += 16) {
        int qcnt = nq - q0; if (qcnt > 16) qcnt = 16;

        unsigned long long acc[4][4];
        #pragma unroll
        for (int qi = 0; qi < 4; qi++)
            #pragma unroll
            for (int pi = 0; pi < 4; pi++) acc[qi][pi] = 0ull;

        for (int h = 0; h < 2; h++) {
            __syncthreads();   // previous phase's smem fully consumed
            if (tid == 0) mbar_expect(mbar, (unsigned)(Npos + 16) * 512u);

            // patch base: position (px0, py0) in padded level (halo offset +4)
            const float* pbase = g_pyr2
                + ((size_t)(b * 2 + h) * TOTPOS + c_lvl_base[lvl]
                   + (size_t)(py0 + 4) * pwp + (px0 + 4)) * 128;
            int nops = Npos + 16;
            for (int i = tid; i < nops; i += 256) {
                if (i < Npos) {
                    int ly = i / pw, lx = i - (i / pw) * pw;
                    bulkcp(Ps_b + (unsigned)(i * PSTRH) * 4u,
                           pbase + ((size_t)ly * pwp + lx) * 128, 512u, mbar);
                } else {
                    int qq = i - Npos;
                    int qv = (qq < qcnt) ? qq : 0;
                    int m = g_qlist[bin * QCAP + q0 + qv];
                    bulkcp(As_b + (unsigned)(qq * PSTRH) * 4u,
                           f1 + ((size_t)b * MM + m) * CC + h * 128, 512u, mbar);
                }
            }
            mbar_wait(mbar, par);
            par ^= 1;

            // ---- GEMM half: 4q x 4pos per thread, f32x2 -------------------
            if (wbase < Npos) {
                #pragma unroll 2
                for (int c = 0; c < 128; c += 4) {
                    ulonglong2 a[4], p[4];
                    #pragma unroll
                    for (int qi = 0; qi < 4; qi++)
                        a[qi] = *(const ulonglong2*)&As[(qsel + 4 * qi) * PSTRH + c];
                    #pragma unroll
                    for (int pi = 0; pi < 4; pi++)
                        p[pi] = *(const ulonglong2*)&Ps[pidx[pi] * PSTRH + c];
                    #pragma unroll
                    for (int qi = 0; qi < 4; qi++)
                        #pragma unroll
                        for (int pi = 0; pi < 4; pi++) {
                            fma2(acc[qi][pi], a[qi].x, p[pi].x);
                            fma2(acc[qi][pi], a[qi].y, p[pi].y);
                        }
                }
            }
        }

        // ---- write D -------------------------------------------------------
        if (wbase < Npos) {
            #pragma unroll
            for (int qi = 0; qi < 4; qi++)
                #pragma unroll
                for (int pi = 0; pi < 4; pi++) {
                    int p = wbase + psel + 8 * pi;
                    if (p < Npos)
                        Ds[(qsel + 4 * qi) * DSTR + p] = unpack_sum(acc[qi][pi]);
                }
        }
        __syncthreads();

        // ---- bilinear epilogue: warp per query -----------------------------
        for (int qq = w; qq < qcnt; qq += 8) {
            int m = g_qlist[bin * QCAP + q0 + qq];
            float cx = cen[((size_t)b * MM + m) * 2 + 0];
            float cy = cen[((size_t)b * MM + m) * 2 + 1];
            float sx = cx * scale, sy = cy * scale;
            float fix = floorf(sx), fiy = floorf(sy);
            float fx = sx - fix, fy = sy - fiy;
            int ox = (int)fix - 4 - px0;
            int oy = (int)fiy - 4 - py0;
            float wx1 = fx, wx0 = 1.f - fx, wy1 = fy, wy0 = 1.f - fy;
            const float* Dq = Ds + qq * DSTR;
            for (int e = lane; e < 81; e += 32) {
                int i = e / 9, j = e - (e / 9) * 9;   // x-offset i-4, y-offset j-4
                int base = (oy + j) * pw + (ox + i);
                float d00 = Dq[base],      d01 = Dq[base + 1];
                float d10 = Dq[base + pw], d11 = Dq[base + pw + 1];
                float val = wy0 * (wx0 * d00 + wx1 * d01)
                          + wy1 * (wx0 * d10 + wx1 * d11);
                out[((size_t)b * 324 + lvl * 81 + e) * MM + m] = val;
            }
        }
    }
}

// ---------------- launch ----------------------------------------------------
extern "C" void kernel_launch(void* const* d_in, const int* in_sizes, int n_in,
                              void* d_out, int out_size) {
    const float* f1  = (const float*)d_in[0];
    const float* f2  = (const float*)d_in[1];
    const float* cen = (const float*)d_in[2];
    float* out = (float*)d_out;

    size_t smem = (size_t)(NPOS_MAX * PSTRH + 16 * PSTRH + 16 * DSTR) * sizeof(float);
    cudaFuncSetAttribute(corr_kernel, cudaFuncAttributeMaxDynamicSharedMemorySize,
                         (int)smem);

    zero_pyr_kernel<<<1024, 256>>>();
    transpose_kernel<<<dim3(HW * HW / 32, CC / 32, BB), dim3(32, 32)>>>(f2);
    pool_kernel<<<BB * 32 * 32, 256>>>(0, 1, 32);
    pool_kernel<<<BB * 16 * 16, 256>>>(1, 2, 16);
    pool_kernel<<<BB * 8 * 8,   256>>>(2, 3, 8);
    zero_cnt_kernel<<<1, 512>>>();
    hist_kernel<<<(BB * MM + 255) / 256, 256>>>(cen);
    corr_kernel<<<NBINS * 4, 256, smem>>>(f1, cen, out);
}